// round 5
// baseline (speedup 1.0000x reference)
#include <cuda_runtime.h>
#include <math.h>

#define H 2048
#define NHEADS 8
#define DHEAD 256
#define SLEN 32
#define NLAYER 3

// ---------------- scratch (static __device__, no allocation) ----------------
__device__ float g_x[SLEN * H];          // running activations (32 x 2048)
__device__ float g_qkv[SLEN * 3 * H];    // QKV (32 x 6144)
__device__ float g_att[SLEN * H];        // attention output pre-proj
__device__ float g_tmp[SLEN * H];        // post-proj + residual (pre-LN)
__device__ float g_ffh[SLEN * 4 * H];    // FF hidden (32 x 8192)
__device__ float g_memv[H];              // cross-attn v (single kv token!)
__device__ float g_co[H];                // cross-attn output row (broadcast)
__device__ float g_h1[H / 2];            // size-predictor hidden
__device__ float g_part[2 * 32 * 4 * H]; // k-split partials (max S*32*N = 512K floats)

__device__ __forceinline__ float gelu_exact(float v) {
    return 0.5f * v * (1.0f + erff(v * 0.7071067811865476f));
}

// ============ packed-fp32 GEMM, M=32, exact arithmetic ============
// Block: 256 threads / 8 warps, covers 32 output cols (warp w -> cols n0+4w..n0+4w+3).
// Lane layout: c = lane&3 (col within warp), kg = lane>>2 (8-way k-interleave).
// Per 32-k group: x read = 1 LDS.128 (8 distinct 16B, broadcast x4 = 128B = 1 phase);
// W read = 1 LDG.128/lane-group covering 4 full 128B lines (perfectly coalesced).
// MACs via fma.rn.f32x2 (packed f32 pairs) into 32 packed accumulators.
// Cross-block k-split S: block (bx, s) computes cols [bx*32,+32) over k slice s,
// writes partial sums to part[(s*32+m)*N + col]; reduce_kernel finishes.
__global__ __launch_bounds__(256) void gemmp_kernel(
    float* __restrict__ part, const float* __restrict__ x, const float* __restrict__ W,
    int N, int K, int S) {
    __shared__ float xs[32 * 256];  // 32 rows x 256-k chunk (32KB)
    const int tid = threadIdx.x, warp = tid >> 5, lane = tid & 31;
    const int c = lane & 3, kg = lane >> 2;
    const int n0 = blockIdx.x * 32, s = blockIdx.y;
    const int klen = K / S, kbeg = s * klen;
    const int col = n0 + warp * 4 + c;
    const float* wrow = W + (size_t)col * K + kbeg + kg * 4;

    unsigned long long acc[32];
#pragma unroll
    for (int m = 0; m < 32; m++) acc[m] = 0ull;

    for (int kc = 0; kc < klen; kc += 256) {
        __syncthreads();
        // stage x[0:32, kbeg+kc : +256): 2048 float4s by 256 threads (coalesced)
#pragma unroll
        for (int it = 0; it < 8; it++) {
            int idx = it * 256 + tid;
            int m = idx >> 6, q = idx & 63;
            *(float4*)&xs[m * 256 + q * 4] =
                *(const float4*)&x[(size_t)m * K + kbeg + kc + q * 4];
        }
        __syncthreads();
#pragma unroll 1
        for (int kq = 0; kq < 8; kq++) {  // each kq covers 32 k (8 kg x 4)
            ulonglong2 wv = *(const ulonglong2*)(wrow + kc + kq * 32);
            const int xoff = kq * 32 + kg * 4;
#pragma unroll
            for (int m = 0; m < 32; m++) {
                ulonglong2 xv = *(const ulonglong2*)&xs[m * 256 + xoff];
                asm("fma.rn.f32x2 %0, %1, %2, %0;" : "+l"(acc[m]) : "l"(xv.x), "l"(wv.x));
                asm("fma.rn.f32x2 %0, %1, %2, %0;" : "+l"(acc[m]) : "l"(xv.y), "l"(wv.y));
            }
        }
    }
    // unpack packed pair, butterfly-sum over the 8 kg groups (xor 4/8/16), store
#pragma unroll
    for (int m = 0; m < 32; m++) {
        float2 f = *reinterpret_cast<float2*>(&acc[m]);
        float r = f.x + f.y;
        r += __shfl_xor_sync(0xffffffffu, r, 4);
        r += __shfl_xor_sync(0xffffffffu, r, 8);
        r += __shfl_xor_sync(0xffffffffu, r, 16);
        if (kg == 0) part[((size_t)s * 32 + m) * N + col] = r;
    }
}

// ============ k-split reduction + bias (+gelu) (+residual) ============
template <int GELU, int RES>
__global__ void reduce_kernel(float* __restrict__ dst, const float* __restrict__ part,
                              const float* __restrict__ bias, const float* __restrict__ resid,
                              int N, int S) {
    int g = blockIdx.x * 256 + threadIdx.x;  // over 32*N
    int m = g / N, n = g - m * N;
    float v = bias[n];
    for (int s = 0; s < S; s++) v += part[((size_t)s * 32 + m) * N + n];
    if (GELU) v = gelu_exact(v);
    if (RES) v += resid[g];
    dst[g] = v;
}

// ---------------- GEMV: out[n] = act(bias[n] + sum_k W[n,k] * x[k]) ----------------
template <int ACT>
__global__ void gemv_kernel(float* __restrict__ out, const float* __restrict__ x,
                            const float* __restrict__ W, const float* __restrict__ bias,
                            int N, int K) {
    int warp = threadIdx.x >> 5, lane = threadIdx.x & 31;
    int n = blockIdx.x * 8 + warp;
    if (n >= N) return;
    const float4* wp = (const float4*)(W + (size_t)n * K);
    const float4* xp = (const float4*)x;
    float acc = 0.f;
    int KQ = K >> 2;
    for (int q = lane; q < KQ; q += 32) {
        float4 w = wp[q], xv = xp[q];
        acc += w.x * xv.x + w.y * xv.y + w.z * xv.z + w.w * xv.w;
    }
#pragma unroll
    for (int o = 16; o; o >>= 1) acc += __shfl_xor_sync(0xffffffffu, acc, o);
    if (lane == 0) {
        float v = acc + bias[n];
        if (ACT == 1) v = gelu_exact(v);
        out[n] = v;
    }
}

// ---------------- size predictor logits + softmax -> out[0:33) ----------------
__global__ void sp_logits_kernel(float* __restrict__ out, const float* __restrict__ h,
                                 const float* __restrict__ W, const float* __restrict__ bias) {
    __shared__ float slog[33];
    int warp = threadIdx.x >> 5, lane = threadIdx.x & 31;
    for (int n = warp; n < 33; n += 8) {
        const float4* wp = (const float4*)(W + (size_t)n * 1024);
        const float4* xp = (const float4*)h;
        float acc = 0.f;
        for (int q = lane; q < 256; q += 32) {
            float4 w = wp[q], xv = xp[q];
            acc += w.x * xv.x + w.y * xv.y + w.z * xv.z + w.w * xv.w;
        }
#pragma unroll
        for (int o = 16; o; o >>= 1) acc += __shfl_xor_sync(0xffffffffu, acc, o);
        if (lane == 0) slog[n] = acc + bias[n];
    }
    __syncthreads();
    if (threadIdx.x == 0) {
        float mx = -1e30f;
        for (int i = 0; i < 33; i++) mx = fmaxf(mx, slog[i]);
        float s = 0.f;
        float e[33];
        for (int i = 0; i < 33; i++) { e[i] = expf(slog[i] - mx); s += e[i]; }
        float inv = 1.f / s;
        for (int i = 0; i < 33; i++) out[i] = e[i] * inv;
    }
}

// ---------------- embedding: x[s] = byte_emb[dec_in[s]] + pos_emb[s] ----------------
__global__ void embed_kernel(const int* __restrict__ tb, const float* __restrict__ bemb,
                             const float* __restrict__ pemb) {
    int s = blockIdx.x;
    int idx = (s == 0) ? 256 : tb[s - 1];
    for (int c = threadIdx.x; c < H; c += blockDim.x)
        g_x[s * H + c] = bemb[(size_t)idx * H + c] + pemb[s * H + c];
}

// ---------------- self-attention (one block per head) ----------------
__global__ void attn_kernel() {
    int head = blockIdx.x;
    __shared__ float sbuf[32 * DHEAD];  // 32KB: q, then reused for v
    __shared__ float satt[32][33];
    int tid = threadIdx.x, warp = tid >> 5, lane = tid & 31;

    for (int r = 0; r < 32; r++) {
        int i = tid + r * 256;
        sbuf[i] = g_qkv[(size_t)(i >> 8) * 3 * H + head * DHEAD + (i & 255)];
    }
    __syncthreads();

#pragma unroll
    for (int r = 0; r < 4; r++) {
        int qi = warp * 4 + r;
        const float4* kp = (const float4*)(g_qkv + (size_t)lane * 3 * H + H + head * DHEAD);
        float s = 0.f;
#pragma unroll 8
        for (int q = 0; q < 64; q++) {
            float4 kv = kp[q];
            s += sbuf[qi * 256 + q * 4 + 0] * kv.x + sbuf[qi * 256 + q * 4 + 1] * kv.y +
                 sbuf[qi * 256 + q * 4 + 2] * kv.z + sbuf[qi * 256 + q * 4 + 3] * kv.w;
        }
        s *= 0.0625f;  // 1/sqrt(256)
        float mx = s;
#pragma unroll
        for (int o = 16; o; o >>= 1) mx = fmaxf(mx, __shfl_xor_sync(0xffffffffu, mx, o));
        float e = expf(s - mx);
        float sum = e;
#pragma unroll
        for (int o = 16; o; o >>= 1) sum += __shfl_xor_sync(0xffffffffu, sum, o);
        satt[qi][lane] = e / sum;
    }
    __syncthreads();

    for (int r = 0; r < 32; r++) {
        int i = tid + r * 256;
        sbuf[i] = g_qkv[(size_t)(i >> 8) * 3 * H + 2 * H + head * DHEAD + (i & 255)];
    }
    __syncthreads();

    for (int r = 0; r < 32; r++) {
        int i = tid + r * 256;
        int qi = i >> 8, d = i & 255;
        float acc = 0.f;
#pragma unroll
        for (int j = 0; j < 32; j++) acc += satt[qi][j] * sbuf[j * 256 + d];
        g_att[(size_t)qi * H + head * DHEAD + d] = acc;
    }
}

// ---------------- LayerNorm (block per row, 512 threads) ----------------
__device__ __forceinline__ float block_reduce(float v, float* red) {
    int lane = threadIdx.x & 31, warp = threadIdx.x >> 5;
#pragma unroll
    for (int o = 16; o; o >>= 1) v += __shfl_xor_sync(0xffffffffu, v, o);
    if (lane == 0) red[warp] = v;
    __syncthreads();
    if (warp == 0) {
        float t = (lane < 16) ? red[lane] : 0.f;
#pragma unroll
        for (int o = 8; o; o >>= 1) t += __shfl_xor_sync(0xffffffffu, t, o);
        if (lane == 0) red[0] = t;
    }
    __syncthreads();
    float r = red[0];
    __syncthreads();
    return r;
}

__global__ void ln_kernel(float* __restrict__ xout, const float* __restrict__ in,
                          const float* __restrict__ addv, const float* __restrict__ g,
                          const float* __restrict__ b) {
    int row = blockIdx.x, tid = threadIdx.x;
    __shared__ float red[16];
    float vals[4];
    float sum = 0.f;
#pragma unroll
    for (int j = 0; j < 4; j++) {
        int c = tid + j * 512;
        float v = in[(size_t)row * H + c];
        if (addv) v += addv[c];
        vals[j] = v;
        sum += v;
    }
    float mean = block_reduce(sum, red) * (1.f / H);
    float s2 = 0.f;
#pragma unroll
    for (int j = 0; j < 4; j++) {
        float d = vals[j] - mean;
        s2 += d * d;
    }
    float var = block_reduce(s2, red) * (1.f / H);
    float rstd = rsqrtf(var + 1e-5f);
#pragma unroll
    for (int j = 0; j < 4; j++) {
        int c = tid + j * 512;
        xout[(size_t)row * H + c] = (vals[j] - mean) * rstd * g[c] + b[c];
    }
}

// ---------------- launch ----------------
extern "C" void kernel_launch(void* const* d_in, const int* in_sizes, int n_in,
                              void* d_out, int out_size) {
    const float* pe       = (const float*)d_in[0];
    const int*   tb       = (const int*)d_in[1];
    const float* sp_w1    = (const float*)d_in[2];
    const float* sp_b1    = (const float*)d_in[3];
    const float* sp_w2    = (const float*)d_in[4];
    const float* sp_b2    = (const float*)d_in[5];
    const float* byte_emb = (const float*)d_in[6];
    const float* pos_emb  = (const float*)d_in[7];
    const float* proj_w   = (const float*)d_in[8];
    const float* proj_b   = (const float*)d_in[9];
    const float* sa_in_w  = (const float*)d_in[10];
    const float* sa_in_b  = (const float*)d_in[11];
    const float* sa_out_w = (const float*)d_in[12];
    const float* sa_out_b = (const float*)d_in[13];
    const float* ca_in_w  = (const float*)d_in[14];
    const float* ca_in_b  = (const float*)d_in[15];
    const float* ca_out_w = (const float*)d_in[16];
    const float* ca_out_b = (const float*)d_in[17];
    const float* ff_w1    = (const float*)d_in[18];
    const float* ff_b1    = (const float*)d_in[19];
    const float* ff_w2    = (const float*)d_in[20];
    const float* ff_b2    = (const float*)d_in[21];
    const float* ln1_g    = (const float*)d_in[22];
    const float* ln1_b    = (const float*)d_in[23];
    const float* ln2_g    = (const float*)d_in[24];
    const float* ln2_b    = (const float*)d_in[25];
    const float* ln3_g    = (const float*)d_in[26];
    const float* ln3_b    = (const float*)d_in[27];
    float* out = (float*)d_out;

    float *x_, *qkv_, *att_, *tmp_, *ffh_, *memv_, *co_, *h1_, *part_;
    cudaGetSymbolAddress((void**)&x_, g_x);
    cudaGetSymbolAddress((void**)&qkv_, g_qkv);
    cudaGetSymbolAddress((void**)&att_, g_att);
    cudaGetSymbolAddress((void**)&tmp_, g_tmp);
    cudaGetSymbolAddress((void**)&ffh_, g_ffh);
    cudaGetSymbolAddress((void**)&memv_, g_memv);
    cudaGetSymbolAddress((void**)&co_, g_co);
    cudaGetSymbolAddress((void**)&h1_, g_h1);
    cudaGetSymbolAddress((void**)&part_, g_part);

    // size predictor head
    gemv_kernel<1><<<1024 / 8, 256>>>(h1_, pe, sp_w1, sp_b1, 1024, H);
    sp_logits_kernel<<<1, 256>>>(out, h1_, sp_w2, sp_b2);

    // decoder input embedding
    embed_kernel<<<32, 256>>>(tb, byte_emb, pos_emb);

    for (int i = 0; i < NLAYER; i++) {
        size_t inw = (size_t)i * 3 * H * H;
        size_t inb = (size_t)i * 3 * H;
        size_t ow  = (size_t)i * H * H;
        size_t ob  = (size_t)i * H;

        // self-attention: QKV (N=6144, K=2048, S=2)
        gemmp_kernel<<<dim3(6144 / 32, 2), 256>>>(part_, x_, sa_in_w + inw, 6144, H, 2);
        reduce_kernel<0, 0><<<(32 * 6144) / 256, 256>>>(qkv_, part_, sa_in_b + inb,
                                                        nullptr, 6144, 2);
        attn_kernel<<<NHEADS, 256>>>();
        // out-proj (N=2048, K=2048, S=4) + residual
        gemmp_kernel<<<dim3(2048 / 32, 4), 256>>>(part_, att_, sa_out_w + ow, 2048, H, 4);
        reduce_kernel<0, 1><<<(32 * 2048) / 256, 256>>>(tmp_, part_, sa_out_b + ob,
                                                        x_, 2048, 4);
        ln_kernel<<<32, 512>>>(x_, tmp_, nullptr, ln1_g + ob, ln1_b + ob);

        // cross-attention with a single kv token: softmax == 1, output is v
        // broadcast -> two GEMVs, independent of queries.
        gemv_kernel<0><<<H / 8, 256>>>(memv_, pe, ca_in_w + inw + (size_t)2 * H * H,
                                       ca_in_b + inb + 2 * H, H, H);
        gemv_kernel<0><<<H / 8, 256>>>(co_, memv_, ca_out_w + ow, ca_out_b + ob, H, H);
        ln_kernel<<<32, 512>>>(x_, x_, co_, ln2_g + ob, ln2_b + ob);

        // feed-forward: ff1 (N=8192, K=2048, S=2) + gelu
        gemmp_kernel<<<dim3(8192 / 32, 2), 256>>>(part_, x_, ff_w1 + (size_t)i * 4 * H * H,
                                                  8192, H, 2);
        reduce_kernel<1, 0><<<(32 * 8192) / 256, 256>>>(ffh_, part_,
                                                        ff_b1 + (size_t)i * 4 * H,
                                                        nullptr, 8192, 2);
        // ff2 (N=2048, K=8192, S=4) + residual
        gemmp_kernel<<<dim3(2048 / 32, 4), 256>>>(part_, ffh_, ff_w2 + (size_t)i * 4 * H * H,
                                                  2048, 4 * H, 4);
        reduce_kernel<0, 1><<<(32 * 2048) / 256, 256>>>(tmp_, part_, ff_b2 + ob, x_, 2048, 4);
        ln_kernel<<<32, 512>>>(x_, tmp_, nullptr, ln3_g + ob, ln3_b + ob);
    }

    // final byte logits (N=256, K=2048, S=8) -> out[33 : 33+32*256)
    gemmp_kernel<<<dim3(256 / 32, 8), 256>>>(part_, x_, proj_w, 256, H, 8);
    reduce_kernel<0, 0><<<(32 * 256) / 256, 256>>>(out + 33, part_, proj_b, nullptr, 256, 8);
}

// round 9
// speedup vs baseline: 1.5238x; 1.5238x over previous
#include <cuda_runtime.h>
#include <math.h>
#include <stdint.h>

#define H 2048
#define NHEADS 8
#define DHEAD 256
#define SLEN 32
#define NLAYER 3

// ---------------- scratch (static __device__, no allocation) ----------------
__device__ __align__(16) float  g_x[SLEN * H];          // activations (plain, for residuals)
__device__ __align__(16) float2 g_x2[SLEN * H];         // activations, tf32 hi/lo split
__device__ __align__(16) float  g_qkv[SLEN * 3 * H];    // QKV (plain, read by attn)
__device__ __align__(16) float2 g_att2[SLEN * H];       // attention out, split
__device__ __align__(16) float2 g_ffh2[SLEN * 4 * H];   // FF hidden (post-gelu), split
__device__ float g_memv[H];                             // cross-attn v (single kv token)
__device__ float g_co[H];                               // cross-attn out row (broadcast)
__device__ float g_h1[H / 2];                           // size-predictor hidden
__device__ __align__(16) float g_part[8 * 32 * 4 * H];  // k-split partials (8MB)

__device__ __forceinline__ float gelu_exact(float v) {
    return 0.5f * v * (1.0f + erff(v * 0.7071067811865476f));
}

// tf32 hi/lo split: v ~= hi + lo with hi,lo tf32-representable; residual ~2^-22.
__device__ __forceinline__ float2 split_tf32(float v) {
    uint32_t hi;
    asm("cvt.rna.tf32.f32 %0, %1;" : "=r"(hi) : "f"(v));
    float hif = __uint_as_float(hi);
    float r = v - hif;
    uint32_t lo;
    asm("cvt.rna.tf32.f32 %0, %1;" : "=r"(lo) : "f"(r));
    return make_float2(hif, __uint_as_float(lo));
}

__device__ __forceinline__ void mma_tf32(float* d, const uint32_t* a, uint32_t b0, uint32_t b1) {
    asm volatile(
        "mma.sync.aligned.m16n8k8.row.col.f32.tf32.tf32.f32 "
        "{%0,%1,%2,%3}, {%4,%5,%6,%7}, {%8,%9}, {%0,%1,%2,%3};"
        : "+f"(d[0]), "+f"(d[1]), "+f"(d[2]), "+f"(d[3])
        : "r"(a[0]), "r"(a[1]), "r"(a[2]), "r"(a[3]), "r"(b0), "r"(b1));
}

// ============ tensor-core GEMM, M=32 (tf32x3, fp32-accurate) ============
// out[m,n] partial = sum over k-slice of x[m,k]*W[n,k].
// Block: 128 thr / 4 warps; warp w covers 32 cols (4 n8-fragments). Block covers n128.
// x2: pre-split (hi,lo) float2, row length K. Staged per 64-k chunk in smem (pitch 68).
// W streamed from gmem (each element read once per k-slice), split on the fly.
// Per k8 step/warp: 8 LDS.64 (A) + 8 LDG.32 (B) + 24 HMMA -> 8192 useful MACs.
__global__ __launch_bounds__(128) void gemmtc_kernel(
    float* __restrict__ part, const float2* __restrict__ x2, const float* __restrict__ W,
    int N, int K, int S) {
    __shared__ float2 xs[32 * 68];  // 32 rows x 64 cols, pitch 68 float2 (17.4KB)
    const int tid = threadIdx.x, warp = tid >> 5, lane = tid & 31;
    const int g = lane >> 2, t = lane & 3;
    const int nblk = blockIdx.x * 128, s = blockIdx.y;
    const int klen = K / S, kbeg = s * klen;
    const int nw = nblk + warp * 32;

    float d[4][2][4];
#pragma unroll
    for (int f = 0; f < 4; f++)
#pragma unroll
        for (int mt = 0; mt < 2; mt++)
#pragma unroll
            for (int r = 0; r < 4; r++) d[f][mt][r] = 0.f;

    // per-fragment W row pointers (rows nw+f*8+g), offset to k = kbeg + t
    const float* wr[4];
#pragma unroll
    for (int f = 0; f < 4; f++) wr[f] = W + (size_t)(nw + f * 8 + g) * K + kbeg + t;

    for (int kc = 0; kc < klen; kc += 64) {
        __syncthreads();
        // stage x2[0:32][kbeg+kc : +64) -> xs  (1024 float4 by 128 threads)
#pragma unroll
        for (int it = 0; it < 8; it++) {
            int idx = it * 128 + tid;
            int m = idx >> 5, q = idx & 31;  // q: float4 units (2 float2)
            *(float4*)&xs[m * 68 + q * 2] =
                *(const float4*)&x2[(size_t)m * K + kbeg + kc + q * 2];
        }
        __syncthreads();

#pragma unroll 1
        for (int step = 0; step < 8; step++) {
            const int kk = step * 8;
            // A fragments (hi & lo) for the two m16 tiles
            uint32_t ah[2][4], al[2][4];
#pragma unroll
            for (int mt = 0; mt < 2; mt++) {
                float2 v0 = xs[(mt * 16 + g) * 68 + kk + t];
                float2 v1 = xs[(mt * 16 + g + 8) * 68 + kk + t];
                float2 v2 = xs[(mt * 16 + g) * 68 + kk + t + 4];
                float2 v3 = xs[(mt * 16 + g + 8) * 68 + kk + t + 4];
                ah[mt][0] = __float_as_uint(v0.x); al[mt][0] = __float_as_uint(v0.y);
                ah[mt][1] = __float_as_uint(v1.x); al[mt][1] = __float_as_uint(v1.y);
                ah[mt][2] = __float_as_uint(v2.x); al[mt][2] = __float_as_uint(v2.y);
                ah[mt][3] = __float_as_uint(v3.x); al[mt][3] = __float_as_uint(v3.y);
            }
#pragma unroll
            for (int f = 0; f < 4; f++) {
                float b0f = wr[f][kc + kk];
                float b1f = wr[f][kc + kk + 4];
                uint32_t b0h, b0l, b1h, b1l;
                asm("cvt.rna.tf32.f32 %0, %1;" : "=r"(b0h) : "f"(b0f));
                asm("cvt.rna.tf32.f32 %0, %1;" : "=r"(b1h) : "f"(b1f));
                float b0r = b0f - __uint_as_float(b0h);
                float b1r = b1f - __uint_as_float(b1h);
                asm("cvt.rna.tf32.f32 %0, %1;" : "=r"(b0l) : "f"(b0r));
                asm("cvt.rna.tf32.f32 %0, %1;" : "=r"(b1l) : "f"(b1r));
#pragma unroll
                for (int mt = 0; mt < 2; mt++) {
                    mma_tf32(d[f][mt], ah[mt], b0h, b1h);  // hi*hi
                    mma_tf32(d[f][mt], al[mt], b0h, b1h);  // lo*hi
                    mma_tf32(d[f][mt], ah[mt], b0l, b1l);  // hi*lo
                }
            }
        }
    }

    // epilogue: D[g][2t],[2t+1] and rows +8; write partials
#pragma unroll
    for (int f = 0; f < 4; f++)
#pragma unroll
        for (int mt = 0; mt < 2; mt++) {
            int col = nw + f * 8 + 2 * t;
            int r0 = mt * 16 + g;
            *(float2*)&part[((size_t)s * 32 + r0) * N + col] =
                make_float2(d[f][mt][0], d[f][mt][1]);
            *(float2*)&part[((size_t)s * 32 + r0 + 8) * N + col] =
                make_float2(d[f][mt][2], d[f][mt][3]);
        }
}

// ============ k-split reduction + bias (plain output) ============
__global__ void reduce_kernel(float* __restrict__ dst, const float* __restrict__ part,
                              const float* __restrict__ bias, int N, int S) {
    int gidx = blockIdx.x * 256 + threadIdx.x;
    int m = gidx / N, n = gidx - m * N;
    float v = bias[n];
    for (int s = 0; s < S; s++) v += part[((size_t)s * 32 + m) * N + n];
    dst[gidx] = v;
}

// ============ k-split reduction + bias + gelu -> split output ============
__global__ void reduce_gelu_split_kernel(float2* __restrict__ dst2,
                                         const float* __restrict__ part,
                                         const float* __restrict__ bias, int N, int S) {
    int gidx = blockIdx.x * 256 + threadIdx.x;
    int m = gidx / N, n = gidx - m * N;
    float v = bias[n];
    for (int s = 0; s < S; s++) v += part[((size_t)s * 32 + m) * N + n];
    dst2[gidx] = split_tf32(gelu_exact(v));
}

// ---------------- block reduce helper ----------------
__device__ __forceinline__ float block_reduce(float v, float* red) {
    int lane = threadIdx.x & 31, warp = threadIdx.x >> 5;
#pragma unroll
    for (int o = 16; o; o >>= 1) v += __shfl_xor_sync(0xffffffffu, v, o);
    if (lane == 0) red[warp] = v;
    __syncthreads();
    if (warp == 0) {
        float t = (lane < 16) ? red[lane] : 0.f;
#pragma unroll
        for (int o = 8; o; o >>= 1) t += __shfl_xor_sync(0xffffffffu, t, o);
        if (lane == 0) red[0] = t;
    }
    __syncthreads();
    float r = red[0];
    __syncthreads();
    return r;
}

// ============ fused: k-split reduce + bias + residual + LayerNorm ============
// block per row (32 blocks, 512 thr). Writes plain x and split x2.
__global__ void lnreduce_kernel(float* __restrict__ xout, float2* __restrict__ xout2,
                                const float* __restrict__ part, const float* __restrict__ bias,
                                const float* __restrict__ resid, const float* __restrict__ g,
                                const float* __restrict__ b, int S) {
    int row = blockIdx.x, tid = threadIdx.x;
    __shared__ float red[16];
    float vals[4];
    float sum = 0.f;
#pragma unroll
    for (int j = 0; j < 4; j++) {
        int c = tid + j * 512;
        float v = bias[c] + resid[(size_t)row * H + c];
        for (int s = 0; s < S; s++) v += part[((size_t)s * 32 + row) * H + c];
        vals[j] = v;
        sum += v;
    }
    float mean = block_reduce(sum, red) * (1.f / H);
    float s2 = 0.f;
#pragma unroll
    for (int j = 0; j < 4; j++) {
        float dd = vals[j] - mean;
        s2 += dd * dd;
    }
    float var = block_reduce(s2, red) * (1.f / H);
    float rstd = rsqrtf(var + 1e-5f);
#pragma unroll
    for (int j = 0; j < 4; j++) {
        int c = tid + j * 512;
        float o = (vals[j] - mean) * rstd * g[c] + b[c];
        xout[(size_t)row * H + c] = o;
        xout2[(size_t)row * H + c] = split_tf32(o);
    }
}

// ============ LN with broadcast add (cross-attn): x = LN(x + co) ============
__global__ void ln_add_kernel(float* __restrict__ xout, float2* __restrict__ xout2,
                              const float* __restrict__ in, const float* __restrict__ addv,
                              const float* __restrict__ g, const float* __restrict__ b) {
    int row = blockIdx.x, tid = threadIdx.x;
    __shared__ float red[16];
    float vals[4];
    float sum = 0.f;
#pragma unroll
    for (int j = 0; j < 4; j++) {
        int c = tid + j * 512;
        float v = in[(size_t)row * H + c] + addv[c];
        vals[j] = v;
        sum += v;
    }
    float mean = block_reduce(sum, red) * (1.f / H);
    float s2 = 0.f;
#pragma unroll
    for (int j = 0; j < 4; j++) {
        float dd = vals[j] - mean;
        s2 += dd * dd;
    }
    float var = block_reduce(s2, red) * (1.f / H);
    float rstd = rsqrtf(var + 1e-5f);
#pragma unroll
    for (int j = 0; j < 4; j++) {
        int c = tid + j * 512;
        float o = (vals[j] - mean) * rstd * g[c] + b[c];
        xout[(size_t)row * H + c] = o;
        xout2[(size_t)row * H + c] = split_tf32(o);
    }
}

// ---------------- GEMV: out[n] = act(bias[n] + sum_k W[n,k] * x[k]) ----------------
template <int ACT>
__global__ void gemv_kernel(float* __restrict__ out, const float* __restrict__ x,
                            const float* __restrict__ W, const float* __restrict__ bias,
                            int N, int K) {
    int warp = threadIdx.x >> 5, lane = threadIdx.x & 31;
    int n = blockIdx.x * 8 + warp;
    if (n >= N) return;
    const float4* wp = (const float4*)(W + (size_t)n * K);
    const float4* xp = (const float4*)x;
    float acc = 0.f;
    int KQ = K >> 2;
    for (int q = lane; q < KQ; q += 32) {
        float4 w = wp[q], xv = xp[q];
        acc += w.x * xv.x + w.y * xv.y + w.z * xv.z + w.w * xv.w;
    }
#pragma unroll
    for (int o = 16; o; o >>= 1) acc += __shfl_xor_sync(0xffffffffu, acc, o);
    if (lane == 0) {
        float v = acc + bias[n];
        if (ACT == 1) v = gelu_exact(v);
        out[n] = v;
    }
}

// ---------------- size predictor logits + softmax -> out[0:33) ----------------
__global__ void sp_logits_kernel(float* __restrict__ out, const float* __restrict__ h,
                                 const float* __restrict__ W, const float* __restrict__ bias) {
    __shared__ float slog[33];
    int warp = threadIdx.x >> 5, lane = threadIdx.x & 31;
    for (int n = warp; n < 33; n += 8) {
        const float4* wp = (const float4*)(W + (size_t)n * 1024);
        const float4* xp = (const float4*)h;
        float acc = 0.f;
        for (int q = lane; q < 256; q += 32) {
            float4 w = wp[q], xv = xp[q];
            acc += w.x * xv.x + w.y * xv.y + w.z * xv.z + w.w * xv.w;
        }
#pragma unroll
        for (int o = 16; o; o >>= 1) acc += __shfl_xor_sync(0xffffffffu, acc, o);
        if (lane == 0) slog[n] = acc + bias[n];
    }
    __syncthreads();
    if (threadIdx.x == 0) {
        float mx = -1e30f;
        for (int i = 0; i < 33; i++) mx = fmaxf(mx, slog[i]);
        float s = 0.f;
        float e[33];
        for (int i = 0; i < 33; i++) { e[i] = expf(slog[i] - mx); s += e[i]; }
        float inv = 1.f / s;
        for (int i = 0; i < 33; i++) out[i] = e[i] * inv;
    }
}

// ---------------- embedding: x[s] = byte_emb[dec_in[s]] + pos_emb[s] ----------------
__global__ void embed_kernel(const int* __restrict__ tb, const float* __restrict__ bemb,
                             const float* __restrict__ pemb) {
    int s = blockIdx.x;
    int idx = (s == 0) ? 256 : tb[s - 1];
    for (int c = threadIdx.x; c < H; c += blockDim.x) {
        float v = bemb[(size_t)idx * H + c] + pemb[s * H + c];
        g_x[s * H + c] = v;
        g_x2[s * H + c] = split_tf32(v);
    }
}

// ---------------- self-attention (one block per head); writes split output ----------------
__global__ void attn_kernel() {
    int head = blockIdx.x;
    __shared__ float sbuf[32 * DHEAD];
    __shared__ float satt[32][33];
    int tid = threadIdx.x, warp = tid >> 5, lane = tid & 31;

    for (int r = 0; r < 32; r++) {
        int i = tid + r * 256;
        sbuf[i] = g_qkv[(size_t)(i >> 8) * 3 * H + head * DHEAD + (i & 255)];
    }
    __syncthreads();

#pragma unroll
    for (int r = 0; r < 4; r++) {
        int qi = warp * 4 + r;
        const float4* kp = (const float4*)(g_qkv + (size_t)lane * 3 * H + H + head * DHEAD);
        float s = 0.f;
#pragma unroll 8
        for (int q = 0; q < 64; q++) {
            float4 kv = kp[q];
            s += sbuf[qi * 256 + q * 4 + 0] * kv.x + sbuf[qi * 256 + q * 4 + 1] * kv.y +
                 sbuf[qi * 256 + q * 4 + 2] * kv.z + sbuf[qi * 256 + q * 4 + 3] * kv.w;
        }
        s *= 0.0625f;
        float mx = s;
#pragma unroll
        for (int o = 16; o; o >>= 1) mx = fmaxf(mx, __shfl_xor_sync(0xffffffffu, mx, o));
        float e = expf(s - mx);
        float sum = e;
#pragma unroll
        for (int o = 16; o; o >>= 1) sum += __shfl_xor_sync(0xffffffffu, sum, o);
        satt[qi][lane] = e / sum;
    }
    __syncthreads();

    for (int r = 0; r < 32; r++) {
        int i = tid + r * 256;
        sbuf[i] = g_qkv[(size_t)(i >> 8) * 3 * H + 2 * H + head * DHEAD + (i & 255)];
    }
    __syncthreads();

    for (int r = 0; r < 32; r++) {
        int i = tid + r * 256;
        int qi = i >> 8, dd = i & 255;
        float acc = 0.f;
#pragma unroll
        for (int j = 0; j < 32; j++) acc += satt[qi][j] * sbuf[j * 256 + dd];
        g_att2[(size_t)qi * H + head * DHEAD + dd] = split_tf32(acc);
    }
}

// ---------------- launch ----------------
extern "C" void kernel_launch(void* const* d_in, const int* in_sizes, int n_in,
                              void* d_out, int out_size) {
    const float* pe       = (const float*)d_in[0];
    const int*   tb       = (const int*)d_in[1];
    const float* sp_w1    = (const float*)d_in[2];
    const float* sp_b1    = (const float*)d_in[3];
    const float* sp_w2    = (const float*)d_in[4];
    const float* sp_b2    = (const float*)d_in[5];
    const float* byte_emb = (const float*)d_in[6];
    const float* pos_emb  = (const float*)d_in[7];
    const float* proj_w   = (const float*)d_in[8];
    const float* proj_b   = (const float*)d_in[9];
    const float* sa_in_w  = (const float*)d_in[10];
    const float* sa_in_b  = (const float*)d_in[11];
    const float* sa_out_w = (const float*)d_in[12];
    const float* sa_out_b = (const float*)d_in[13];
    const float* ca_in_w  = (const float*)d_in[14];
    const float* ca_in_b  = (const float*)d_in[15];
    const float* ca_out_w = (const float*)d_in[16];
    const float* ca_out_b = (const float*)d_in[17];
    const float* ff_w1    = (const float*)d_in[18];
    const float* ff_b1    = (const float*)d_in[19];
    const float* ff_w2    = (const float*)d_in[20];
    const float* ff_b2    = (const float*)d_in[21];
    const float* ln1_g    = (const float*)d_in[22];
    const float* ln1_b    = (const float*)d_in[23];
    const float* ln2_g    = (const float*)d_in[24];
    const float* ln2_b    = (const float*)d_in[25];
    const float* ln3_g    = (const float*)d_in[26];
    const float* ln3_b    = (const float*)d_in[27];
    float* out = (float*)d_out;

    float *x_, *qkv_, *memv_, *co_, *h1_, *part_;
    float2 *x2_, *att2_, *ffh2_;
    cudaGetSymbolAddress((void**)&x_, g_x);
    cudaGetSymbolAddress((void**)&x2_, g_x2);
    cudaGetSymbolAddress((void**)&qkv_, g_qkv);
    cudaGetSymbolAddress((void**)&att2_, g_att2);
    cudaGetSymbolAddress((void**)&ffh2_, g_ffh2);
    cudaGetSymbolAddress((void**)&memv_, g_memv);
    cudaGetSymbolAddress((void**)&co_, g_co);
    cudaGetSymbolAddress((void**)&h1_, g_h1);
    cudaGetSymbolAddress((void**)&part_, g_part);

    // size predictor head
    gemv_kernel<1><<<1024 / 8, 256>>>(h1_, pe, sp_w1, sp_b1, 1024, H);
    sp_logits_kernel<<<1, 256>>>(out, h1_, sp_w2, sp_b2);

    // decoder input embedding (writes x and x2)
    embed_kernel<<<32, 256>>>(tb, byte_emb, pos_emb);

    for (int i = 0; i < NLAYER; i++) {
        size_t inw = (size_t)i * 3 * H * H;
        size_t inb = (size_t)i * 3 * H;
        size_t ow  = (size_t)i * H * H;
        size_t ob  = (size_t)i * H;

        // QKV: N=6144, K=2048, S=8 (48x8 = 384 blocks)
        gemmtc_kernel<<<dim3(6144 / 128, 8), 128>>>(part_, x2_, sa_in_w + inw, 6144, H, 8);
        reduce_kernel<<<(32 * 6144) / 256, 256>>>(qkv_, part_, sa_in_b + inb, 6144, 8);
        attn_kernel<<<NHEADS, 256>>>();
        // out-proj: N=2048, K=2048, S=16 (16x16 = 256 blocks); fused reduce+resid+LN
        gemmtc_kernel<<<dim3(2048 / 128, 16), 128>>>(part_, att2_, sa_out_w + ow, 2048, H, 16);
        lnreduce_kernel<<<32, 512>>>(x_, x2_, part_, sa_out_b + ob, x_, ln1_g + ob,
                                     ln1_b + ob, 16);

        // cross-attention, single kv token: output = v broadcast -> two GEMVs
        gemv_kernel<0><<<H / 8, 256>>>(memv_, pe, ca_in_w + inw + (size_t)2 * H * H,
                                       ca_in_b + inb + 2 * H, H, H);
        gemv_kernel<0><<<H / 8, 256>>>(co_, memv_, ca_out_w + ow, ca_out_b + ob, H, H);
        ln_add_kernel<<<32, 512>>>(x_, x2_, x_, co_, ln2_g + ob, ln2_b + ob);

        // ff1: N=8192, K=2048, S=8 (64x8 = 512 blocks); gelu + split
        gemmtc_kernel<<<dim3(8192 / 128, 8), 128>>>(part_, x2_, ff_w1 + (size_t)i * 4 * H * H,
                                                    8192, H, 8);
        reduce_gelu_split_kernel<<<(32 * 8192) / 256, 256>>>(ffh2_, part_,
                                                             ff_b1 + (size_t)i * 4 * H,
                                                             8192, 8);
        // ff2: N=2048, K=8192, S=16 (16x16 = 256 blocks); fused reduce+resid+LN
        gemmtc_kernel<<<dim3(2048 / 128, 16), 128>>>(part_, ffh2_,
                                                     ff_w2 + (size_t)i * 4 * H * H,
                                                     2048, 4 * H, 16);
        lnreduce_kernel<<<32, 512>>>(x_, x2_, part_, ff_b2 + ob, x_, ln3_g + ob,
                                     ln3_b + ob, 16);
    }

    // final byte logits: N=256, K=2048, S=16 -> out[33 : 33+32*256)
    gemmtc_kernel<<<dim3(256 / 128, 16), 128>>>(part_, x2_, proj_w, 256, H, 16);
    reduce_kernel<<<(32 * 256) / 256, 256>>>(out + 33, part_, proj_b, 256, 16);
}